// round 4
// baseline (speedup 1.0000x reference)
#include <cuda_runtime.h>

#define N_NODES 50000
#define E_EDGES 800000
#define IN_DIM  128
#define NHEAD   8
#define HD      128          // H*D

#define SCAN_BLK 512
#define SCAN_NB  ((N_NODES + SCAN_BLK - 1) / SCAN_BLK)   // 98

// Scratch (static __device__ — no allocation allowed)
__device__ float g_q [(size_t)N_NODES * HD];        // 25.6 MB (per-node reads)
__device__ float g_kv[(size_t)N_NODES * 2 * HD];    // 51.2 MB: K | V per node
__device__ int   g_deg[N_NODES];
__device__ int   g_off[N_NODES];      // exclusive scan of deg
__device__ int   g_cursor[N_NODES];   // scatter cursors
__device__ int   g_bsum[SCAN_NB];
__device__ int   g_boff[SCAN_NB];
__device__ int   g_esrc[E_EDGES];     // src node per edge, grouped by dst

// ---------------------------------------------------------------------------
__global__ void zero_deg_kernel() {
    int i = blockIdx.x * blockDim.x + threadIdx.x;
    if (i < N_NODES) g_deg[i] = 0;
}

__global__ void hist_kernel(const int* __restrict__ dst) {
    int e = blockIdx.x * blockDim.x + threadIdx.x;
    if (e < E_EDGES) atomicAdd(&g_deg[dst[e]], 1);
}

// Block-local inclusive scan -> exclusive per-element + block sums
__global__ __launch_bounds__(SCAN_BLK) void scan1_kernel() {
    __shared__ int sd[SCAN_BLK];
    int t = threadIdx.x;
    int i = blockIdx.x * SCAN_BLK + t;
    int v = (i < N_NODES) ? g_deg[i] : 0;
    sd[t] = v;
    __syncthreads();
    #pragma unroll
    for (int off = 1; off < SCAN_BLK; off <<= 1) {
        int add = (t >= off) ? sd[t - off] : 0;
        __syncthreads();
        sd[t] += add;
        __syncthreads();
    }
    if (i < N_NODES) g_off[i] = sd[t] - v;
    if (t == SCAN_BLK - 1) g_bsum[blockIdx.x] = sd[t];
}

// Scan the 98 block sums (single block)
__global__ void scan2_kernel() {
    __shared__ int sb[SCAN_NB];
    int t = threadIdx.x;
    if (t < SCAN_NB) sb[t] = g_bsum[t];
    __syncthreads();
    if (t == 0) {
        int run = 0;
        for (int b = 0; b < SCAN_NB; b++) { int x = sb[b]; sb[b] = run; run += x; }
    }
    __syncthreads();
    if (t < SCAN_NB) g_boff[t] = sb[t];
}

__global__ void scan3_kernel() {
    int i = blockIdx.x * blockDim.x + threadIdx.x;
    if (i < N_NODES) {
        int o = g_off[i] + g_boff[i >> 9];   // 9 = log2(SCAN_BLK)
        g_off[i] = o;
        g_cursor[i] = o;
    }
}

// Scatter src ids into dst-grouped buckets
__global__ void scatter_kernel(const int* __restrict__ src,
                               const int* __restrict__ dst) {
    int e = blockIdx.x * blockDim.x + threadIdx.x;
    if (e >= E_EDGES) return;
    int pos = atomicAdd(&g_cursor[dst[e]], 1);
    g_esrc[pos] = src[e];
}

// ---------------------------------------------------------------------------
// QKV projection. BM=64, BN=64, BK=16, 256 threads, 4x4 register tile.
// grid.y in [0,6): proj = y>>1, column half = (y&1)*64
// proj 0 -> g_q[row][c]; proj 1 -> g_kv[row][c]; proj 2 -> g_kv[row][128+c]
// ---------------------------------------------------------------------------
__global__ __launch_bounds__(256) void qkv_kernel(
    const float* __restrict__ h,
    const float* __restrict__ Wq, const float* __restrict__ bq,
    const float* __restrict__ Wk, const float* __restrict__ bk,
    const float* __restrict__ Wv, const float* __restrict__ bv)
{
    __shared__ float As[16][68];   // [k][m], padded
    __shared__ float Bs[16][64];   // [k][n]

    const int tid = threadIdx.x;
    const int tx  = tid & 15;
    const int ty  = tid >> 4;
    const int m0  = blockIdx.x * 64;
    const int by  = blockIdx.y;
    const int proj = by >> 1;
    const int c0   = (by & 1) * 64;

    const float* W = (proj == 0) ? Wq : (proj == 1) ? Wk : Wv;
    const float* b = (proj == 0) ? bq : (proj == 1) ? bk : bv;

    const int lrow = tid >> 2;          // 0..63
    const int lkg  = (tid & 3) * 4;     // 0,4,8,12
    const int grow = m0 + lrow;
    const int wkk  = tid >> 4;          // 0..15
    const int wng  = (tid & 15) * 4;    // 0..60

    float acc[4][4] = {};

    for (int k0 = 0; k0 < IN_DIM; k0 += 16) {
        float4 hv = make_float4(0.f, 0.f, 0.f, 0.f);
        if (grow < N_NODES)
            hv = __ldg((const float4*)&h[(size_t)grow * IN_DIM + k0 + lkg]);
        float4 wv = __ldg((const float4*)&W[(size_t)(k0 + wkk) * HD + c0 + wng]);

        As[lkg + 0][lrow] = hv.x;
        As[lkg + 1][lrow] = hv.y;
        As[lkg + 2][lrow] = hv.z;
        As[lkg + 3][lrow] = hv.w;
        *(float4*)&Bs[wkk][wng] = wv;
        __syncthreads();

        #pragma unroll
        for (int kk = 0; kk < 16; kk++) {
            float4 a4 = *(float4*)&As[kk][ty * 4];
            float4 b4 = *(float4*)&Bs[kk][tx * 4];
            float av[4] = {a4.x, a4.y, a4.z, a4.w};
            float bw[4] = {b4.x, b4.y, b4.z, b4.w};
            #pragma unroll
            for (int i = 0; i < 4; i++)
                #pragma unroll
                for (int j = 0; j < 4; j++)
                    acc[i][j] += av[i] * bw[j];
        }
        __syncthreads();
    }

    // destination base
    float* dstbuf;
    size_t stride;
    int    coff = c0 + tx * 4;
    if (proj == 0) { dstbuf = g_q;  stride = HD;     }
    else           { dstbuf = g_kv; stride = 2 * HD; coff += (proj == 2) ? HD : 0; }

    float4 bb = __ldg((const float4*)&b[c0 + tx * 4]);
    float bl[4] = {bb.x, bb.y, bb.z, bb.w};
    #pragma unroll
    for (int i = 0; i < 4; i++) {
        int row = m0 + ty * 4 + i;
        if (row < N_NODES) {
            float4 o;
            o.x = acc[i][0] + bl[0];
            o.y = acc[i][1] + bl[1];
            o.z = acc[i][2] + bl[2];
            o.w = acc[i][3] + bl[3];
            *(float4*)&dstbuf[(size_t)row * stride + coff] = o;
        }
    }
}

// ---------------------------------------------------------------------------
// Node kernel: one warp per dst node. No atomics.
// lane t: float4 over dims [4t,4t+4), head = t>>2 (4 lanes per head).
// ---------------------------------------------------------------------------
__global__ __launch_bounds__(256) void node_kernel(
    const float* __restrict__ dis,
    const float* __restrict__ att_w, const float* __restrict__ att_b,
    float* __restrict__ out)
{
    const int warp = (blockIdx.x * blockDim.x + threadIdx.x) >> 5;
    const int lane = threadIdx.x & 31;
    if (warp >= N_NODES) return;
    const int n = warp;

    // hoist CSR range so its latency overlaps the Q gather
    const int start = __ldg(&g_off[n]);
    const int deg   = __ldg(&g_deg[n]);
    const int end   = start + deg;

    const float4* kv4 = (const float4*)g_kv;
    const float4  q   = __ldg(((const float4*)g_q) + (size_t)n * 32 + lane);

    const int head = lane >> 2;
    const float bias = __ldg(&dis[n]) * __ldg(&att_w[head]) + __ldg(&att_b[head]);

    float4 acc = make_float4(0.f, 0.f, 0.f, 0.f);
    float z = 0.f;

    int i = start;
    // 4-edge unrolled main loop: 8 outstanding LDG.128/lane for latency hiding
    for (; i + 4 <= end; i += 4) {
        int s0 = __ldg(&g_esrc[i]);
        int s1 = __ldg(&g_esrc[i + 1]);
        int s2 = __ldg(&g_esrc[i + 2]);
        int s3 = __ldg(&g_esrc[i + 3]);
        size_t r0 = (size_t)s0 * 64, r1 = (size_t)s1 * 64;
        size_t r2 = (size_t)s2 * 64, r3 = (size_t)s3 * 64;
        // issue all 8 loads up front
        float4 k0 = __ldg(kv4 + r0 + lane),      k1 = __ldg(kv4 + r1 + lane);
        float4 k2 = __ldg(kv4 + r2 + lane),      k3 = __ldg(kv4 + r3 + lane);
        float4 v0 = __ldg(kv4 + r0 + 32 + lane), v1 = __ldg(kv4 + r1 + 32 + lane);
        float4 v2 = __ldg(kv4 + r2 + 32 + lane), v3 = __ldg(kv4 + r3 + 32 + lane);

        float p0 = q.x * k0.x + q.y * k0.y + q.z * k0.z + q.w * k0.w;
        float p1 = q.x * k1.x + q.y * k1.y + q.z * k1.z + q.w * k1.w;
        float p2 = q.x * k2.x + q.y * k2.y + q.z * k2.z + q.w * k2.w;
        float p3 = q.x * k3.x + q.y * k3.y + q.z * k3.z + q.w * k3.w;
        p0 += __shfl_xor_sync(0xffffffffu, p0, 1);
        p0 += __shfl_xor_sync(0xffffffffu, p0, 2);
        p1 += __shfl_xor_sync(0xffffffffu, p1, 1);
        p1 += __shfl_xor_sync(0xffffffffu, p1, 2);
        p2 += __shfl_xor_sync(0xffffffffu, p2, 1);
        p2 += __shfl_xor_sync(0xffffffffu, p2, 2);
        p3 += __shfl_xor_sync(0xffffffffu, p3, 1);
        p3 += __shfl_xor_sync(0xffffffffu, p3, 2);

        float e0 = __expf(fminf(fmaxf((p0 + bias) * 0.25f, -5.0f), 5.0f));
        float e1 = __expf(fminf(fmaxf((p1 + bias) * 0.25f, -5.0f), 5.0f));
        float e2 = __expf(fminf(fmaxf((p2 + bias) * 0.25f, -5.0f), 5.0f));
        float e3 = __expf(fminf(fmaxf((p3 + bias) * 0.25f, -5.0f), 5.0f));

        acc.x += v0.x * e0 + v1.x * e1 + v2.x * e2 + v3.x * e3;
        acc.y += v0.y * e0 + v1.y * e1 + v2.y * e2 + v3.y * e3;
        acc.z += v0.z * e0 + v1.z * e1 + v2.z * e2 + v3.z * e3;
        acc.w += v0.w * e0 + v1.w * e1 + v2.w * e2 + v3.w * e3;
        z += e0 + e1 + e2 + e3;
    }
    for (; i < end; i++) {
        int s = __ldg(&g_esrc[i]);
        size_t r = (size_t)s * 64;
        float4 k = __ldg(kv4 + r + lane);
        float4 v = __ldg(kv4 + r + 32 + lane);
        float p = q.x * k.x + q.y * k.y + q.z * k.z + q.w * k.w;
        p += __shfl_xor_sync(0xffffffffu, p, 1);
        p += __shfl_xor_sync(0xffffffffu, p, 2);
        float ex = __expf(fminf(fmaxf((p + bias) * 0.25f, -5.0f), 5.0f));
        acc.x += v.x * ex;
        acc.y += v.y * ex;
        acc.z += v.z * ex;
        acc.w += v.w * ex;
        z += ex;
    }

    float inv = 1.0f / z;   // deg-0 node -> NaN, matches reference 0/0
    float4 o;
    o.x = acc.x * inv; o.y = acc.y * inv; o.z = acc.z * inv; o.w = acc.w * inv;
    *(float4*)&out[(size_t)n * HD + lane * 4] = o;
}

// ---------------------------------------------------------------------------
extern "C" void kernel_launch(void* const* d_in, const int* in_sizes, int n_in,
                              void* d_out, int out_size) {
    const float* h     = (const float*)d_in[0];
    const float* dis   = (const float*)d_in[1];
    const float* Wq    = (const float*)d_in[2];
    const float* bq    = (const float*)d_in[3];
    const float* Wk    = (const float*)d_in[4];
    const float* bk    = (const float*)d_in[5];
    const float* Wv    = (const float*)d_in[6];
    const float* bv    = (const float*)d_in[7];
    const float* att_w = (const float*)d_in[8];
    const float* att_b = (const float*)d_in[9];
    const int*   src   = (const int*)d_in[10];
    const int*   dst   = (const int*)d_in[11];
    float* out = (float*)d_out;

    const int EB = 256;

    // CSR build (dst-grouped edge buckets)
    zero_deg_kernel<<<(N_NODES + EB - 1) / EB, EB>>>();
    hist_kernel<<<(E_EDGES + EB - 1) / EB, EB>>>(dst);
    scan1_kernel<<<SCAN_NB, SCAN_BLK>>>();
    scan2_kernel<<<1, 128>>>();
    scan3_kernel<<<(N_NODES + EB - 1) / EB, EB>>>();
    scatter_kernel<<<(E_EDGES + EB - 1) / EB, EB>>>(src, dst);

    // QKV projection
    dim3 g((N_NODES + 63) / 64, 6);
    qkv_kernel<<<g, 256>>>(h, Wq, bq, Wk, bk, Wv, bv);

    // One warp per node, atomic-free accumulate + normalize
    node_kernel<<<(N_NODES * 32 + EB - 1) / EB, EB>>>(dis, att_w, att_b, out);
}